// round 13
// baseline (speedup 1.0000x reference)
#include <cuda_runtime.h>
#include <cstdint>

// HadamardTransform: y[b,:,h,w] = (H_1024 @ pad(x[b,:,h,w]))[0:768] / 32
// FWHT-1024 per pixel, two register passes over channel bits (5-9 then 0-4),
// packed f32x2 math (2 pixels per thread), 64-bit gmem/smem ops throughout.
// Champion R5/R12 schedule shape; pass 1 zero-padding eliminated analytically
// (24 live u64, 112 packed ops instead of 160, same stage-parallel ordering).

#define DIMC          768
#define TILE          16          // pixels per CTA
#define THREADS       256
#define PIX_PER_IMG   3136        // 56*56
#define TILES_PER_IMG 196         // 3136/16

// ---- packed f32x2 ops (sm_103a) ----
__device__ __forceinline__ uint64_t addx2(uint64_t a, uint64_t b) {
    uint64_t d; asm("add.rn.f32x2 %0, %1, %2;" : "=l"(d) : "l"(a), "l"(b)); return d;
}
__device__ __forceinline__ uint64_t subx2(uint64_t a, uint64_t b) {
    const uint64_t NEG1 = 0xBF800000BF800000ULL;   // (-1.0f, -1.0f)
    uint64_t d; asm("fma.rn.f32x2 %0, %1, %2, %3;" : "=l"(d) : "l"(b), "l"(NEG1), "l"(a)); return d;
}
__device__ __forceinline__ uint64_t mulx2(uint64_t a, uint64_t b) {
    uint64_t d; asm("mul.rn.f32x2 %0, %1, %2;" : "=l"(d) : "l"(a), "l"(b)); return d;
}

// smem layout (u64 units): row r (0..767) at (r + (r>>5))*8 + p2.
// Conflict-free 64-bit LDS/STS in both passes (32-row stride == 16 mod 32 banks).

__global__ __launch_bounds__(THREADS, 3)
void fwht1024_kernel(const float* __restrict__ x, float* __restrict__ y) {
    extern __shared__ uint64_t s[];   // 792*8 = 6336 u64 = 50688 B

    const int tid = threadIdx.x;
    const int T   = blockIdx.x;
    const int b   = T / TILES_PER_IMG;
    const int p0  = (T % TILES_PER_IMG) * TILE;

    const int p2 = tid & 7;        // pixel pair -> pixels 2*p2, 2*p2+1
    const int g  = tid >> 3;       // 0..31

    const size_t base = (size_t)b * DIMC * PIX_PER_IMG + p0 + 2 * p2;

    // ---- Pass 1: FWHT32 over channel bits 5..9 (c = j*32+g), gmem -> smem.
    // Channels j >= 24 are zero; their butterflies are folded out:
    //  * stages m=1,2,4: zero block stays zero -> run only on j < 24
    //  * stage m=8: pairs (16..23 | 24..31) are copies -> w[24+i] aliases w[16+i]
    //  * stage m=16: j=8..15 pair with the alias (w[j+16]==w[j+8]); their
    //    minus-outputs (k_hi >= 24) are discarded -> single add each.
    {
        uint64_t w[24];
        // ALL loads first: 24 independent LDG.64 -> full MLP
        #pragma unroll
        for (int j = 0; j < 24; j++) {
            const float2 v = *(const float2*)(x + base +
                               (size_t)(j * 32 + g) * PIX_PER_IMG);
            uint64_t u;
            asm("mov.b64 %0, {%1, %2};" : "=l"(u) : "f"(v.x), "f"(v.y));
            w[j] = u;
        }

        // stages m = 1, 2, 4 (pairs stay within each aligned 8-block)
        #pragma unroll
        for (int st = 0; st < 3; st++) {
            const int m = 1 << st;
            #pragma unroll
            for (int j = 0; j < 24; j++) {
                if (!(j & m)) {
                    uint64_t a = w[j], c2 = w[j + m];
                    w[j]     = addx2(a, c2);
                    w[j + m] = subx2(a, c2);
                }
            }
        }

        // stage m = 8: only block pair (0,1); block 2 pairs zeros (no-op)
        #pragma unroll
        for (int j = 0; j < 8; j++) {
            uint64_t a = w[j], c2 = w[j + 8];
            w[j]     = addx2(a, c2);
            w[j + 8] = subx2(a, c2);
        }

        // stage m = 16: j=8..15 first (reads old w[16..23] via alias),
        // then j=0..7 (updates w[0..7] and w[16..23]).
        #pragma unroll
        for (int j = 8; j < 16; j++)
            w[j] = addx2(w[j], w[j + 8]);
        #pragma unroll
        for (int j = 0; j < 8; j++) {
            uint64_t a = w[j], c2 = w[j + 16];
            w[j]      = addx2(a, c2);
            w[j + 16] = subx2(a, c2);
        }

        // store intermediates t[0..23] (k_hi >= 24 never read downstream)
        #pragma unroll
        for (int j = 0; j < 24; j++)
            s[(j * 33 + g) * 8 + p2] = w[j];
    }
    __syncthreads();

    // ---- Pass 2: butterfly over channel bits 0..4, smem -> gmem ----
    if (g < 24) {
        uint64_t w[32];
        #pragma unroll
        for (int j = 0; j < 32; j++)
            w[j] = s[(g * 33 + j) * 8 + p2];

        #pragma unroll
        for (int st = 0; st < 5; st++) {
            const int m = 1 << st;
            #pragma unroll
            for (int j = 0; j < 32; j++) {
                if (!(j & m)) {
                    uint64_t a = w[j], c2 = w[j + m];
                    w[j]     = addx2(a, c2);
                    w[j + m] = subx2(a, c2);
                }
            }
        }

        const uint64_t SCALE = 0x3D0000003D000000ULL;   // (1/32, 1/32)
        #pragma unroll
        for (int j = 0; j < 32; j++) {
            uint64_t r = mulx2(w[j], SCALE);
            float lo, hi;
            asm("mov.b64 {%0, %1}, %2;" : "=f"(lo), "=f"(hi) : "l"(r));
            *(float2*)(y + base + (size_t)(g * 32 + j) * PIX_PER_IMG)
                = make_float2(lo, hi);
        }
    }
}

extern "C" void kernel_launch(void* const* d_in, const int* in_sizes, int n_in,
                              void* d_out, int out_size) {
    (void)in_sizes; (void)n_in; (void)out_size;
    const float* x = (const float*)d_in[0];
    float* y = (float*)d_out;

    const int smem_bytes = 792 * 8 * sizeof(uint64_t);   // 50688
    cudaFuncSetAttribute(fwht1024_kernel,
                         cudaFuncAttributeMaxDynamicSharedMemorySize, smem_bytes);

    const int grid = 16 * TILES_PER_IMG;   // 3136 tiles
    fwht1024_kernel<<<grid, THREADS, smem_bytes>>>(x, y);
}

// round 14
// speedup vs baseline: 1.0304x; 1.0304x over previous
#include <cuda_runtime.h>
#include <cstdint>

// HadamardTransform: y[b,:,h,w] = (H_1024 @ pad(x[b,:,h,w]))[0:768] / 32
// FWHT-1024 per pixel, two register passes over channel bits (5-9 then 0-4),
// packed f32x2 math (2 pixels per thread), 64-bit gmem/smem ops throughout.
// Champion R5/R12 configuration: TILE=16, 256 threads, 3 CTAs/SM, monolithic
// FWHT32 passes, batched loads for full MLP, direct gmem I/O in both passes.
// Pass-1 loads carry an L2::256B prefetch hint: the adjacent 64B of each
// channel row belongs to the co-resident neighbor CTA's tile -> cross-CTA
// L2 warming at zero extra instruction cost.

#define DIMC          768
#define TILE          16          // pixels per CTA
#define THREADS       256
#define PIX_PER_IMG   3136        // 56*56
#define TILES_PER_IMG 196         // 3136/16

// ---- packed f32x2 ops (sm_103a) ----
__device__ __forceinline__ uint64_t addx2(uint64_t a, uint64_t b) {
    uint64_t d; asm("add.rn.f32x2 %0, %1, %2;" : "=l"(d) : "l"(a), "l"(b)); return d;
}
__device__ __forceinline__ uint64_t subx2(uint64_t a, uint64_t b) {
    const uint64_t NEG1 = 0xBF800000BF800000ULL;   // (-1.0f, -1.0f)
    uint64_t d; asm("fma.rn.f32x2 %0, %1, %2, %3;" : "=l"(d) : "l"(b), "l"(NEG1), "l"(a)); return d;
}
__device__ __forceinline__ uint64_t mulx2(uint64_t a, uint64_t b) {
    uint64_t d; asm("mul.rn.f32x2 %0, %1, %2;" : "=l"(d) : "l"(a), "l"(b)); return d;
}

// 64-bit non-coherent load with 256B L2 prefetch (pulls the neighbor tile's
// sectors of the same channel row into L2).
__device__ __forceinline__ uint64_t ldg64_pf256(const float* p) {
    uint64_t d;
    asm("ld.global.nc.L2::256B.b64 %0, [%1];" : "=l"(d) : "l"(p));
    return d;
}

// smem layout (float2 units): row r (0..767) at (r + (r>>5))*8 + p2.
// The per-32-row pad makes both passes' 16-lane LDS/STS.64 phases
// conflict-free (32-row stride = 528 words == 16 mod 32).

__global__ __launch_bounds__(THREADS, 3)
void fwht1024_kernel(const float* __restrict__ x, float* __restrict__ y) {
    extern __shared__ uint64_t s[];   // 792*8 = 6336 u64 = 50688 B

    const int tid = threadIdx.x;
    const int T   = blockIdx.x;
    const int b   = T / TILES_PER_IMG;
    const int p0  = (T % TILES_PER_IMG) * TILE;

    const int p2 = tid & 7;        // pixel pair -> pixels 2*p2, 2*p2+1
    const int g  = tid >> 3;       // 0..31

    const size_t base = (size_t)b * DIMC * PIX_PER_IMG + p0 + 2 * p2;

    // ---- Pass 1: butterfly over channel bits 5..9, gmem -> smem ----
    // Thread owns channels c = j*32 + g; j >= 24 are zero padding.
    {
        uint64_t w[32];
        #pragma unroll
        for (int j = 0; j < 24; j++)
            w[j] = ldg64_pf256(x + base + (size_t)(j * 32 + g) * PIX_PER_IMG);
        #pragma unroll
        for (int j = 24; j < 32; j++)
            w[j] = 0ULL;

        #pragma unroll
        for (int st = 0; st < 5; st++) {
            const int m = 1 << st;
            #pragma unroll
            for (int j = 0; j < 32; j++) {
                if (!(j & m)) {
                    uint64_t a = w[j], c2 = w[j + m];
                    w[j]     = addx2(a, c2);
                    w[j + m] = subx2(a, c2);
                }
            }
        }

        // only intermediates with j < 24 are ever read (outputs keep k < 768)
        #pragma unroll
        for (int j = 0; j < 24; j++)
            s[(j * 33 + g) * 8 + p2] = w[j];
    }
    __syncthreads();

    // ---- Pass 2: butterfly over channel bits 0..4, smem -> gmem ----
    if (g < 24) {
        uint64_t w[32];
        #pragma unroll
        for (int j = 0; j < 32; j++)
            w[j] = s[(g * 33 + j) * 8 + p2];

        #pragma unroll
        for (int st = 0; st < 5; st++) {
            const int m = 1 << st;
            #pragma unroll
            for (int j = 0; j < 32; j++) {
                if (!(j & m)) {
                    uint64_t a = w[j], c2 = w[j + m];
                    w[j]     = addx2(a, c2);
                    w[j + m] = subx2(a, c2);
                }
            }
        }

        const uint64_t SCALE = 0x3D0000003D000000ULL;   // (1/32, 1/32)
        #pragma unroll
        for (int j = 0; j < 32; j++) {
            uint64_t r = mulx2(w[j], SCALE);
            float lo, hi;
            asm("mov.b64 {%0, %1}, %2;" : "=f"(lo), "=f"(hi) : "l"(r));
            *(float2*)(y + base + (size_t)(g * 32 + j) * PIX_PER_IMG)
                = make_float2(lo, hi);
        }
    }
}

extern "C" void kernel_launch(void* const* d_in, const int* in_sizes, int n_in,
                              void* d_out, int out_size) {
    (void)in_sizes; (void)n_in; (void)out_size;
    const float* x = (const float*)d_in[0];
    float* y = (float*)d_out;

    const int smem_bytes = 792 * 8 * sizeof(uint64_t);   // 50688
    cudaFuncSetAttribute(fwht1024_kernel,
                         cudaFuncAttributeMaxDynamicSharedMemorySize, smem_bytes);

    const int grid = 16 * TILES_PER_IMG;   // 3136 tiles
    fwht1024_kernel<<<grid, THREADS, smem_bytes>>>(x, y);
}